// round 14
// baseline (speedup 1.0000x reference)
#include <cuda_runtime.h>
#include <math.h>

#define NB   8
#define C    128
#define H    56
#define W    56
#define O    64
#define NC   2
#define KS   5
#define P    25
#define P2   50           // NC * P
#define HW   (H * W)      // 3136
#define PIX  (NB * HW)    // 25088
#define CP   (C * P)      // 3200
#define CP4  (CP / 4)     // 800 float4 per o-row
#define C4   (C / 4)      // 32

typedef unsigned long long u64;

// Scratch (allocation-free rule: __device__ globals)
__device__ __align__(16) float g_V[P2 * C];  // folded weights V[k*P+p][c]
__device__ float g_const[NC];                // per-class constant
__device__ float g_Y[NB * P * HW * 2];       // Y[n][p][hw][{class0,class1}]

// Launch-invariant weights staged to the constant port (off the LSU).
__constant__ ulonglong2 c_V[P2 * C4];        // 25.6 KB, same layout as g_V

__device__ __forceinline__ void fma2(u64& d, u64 a, u64 b) {
    asm("fma.rn.f32x2 %0, %1, %2, %0;" : "+l"(d) : "l"(a), "l"(b));
}
__device__ __forceinline__ u64 pack2(float lo, float hi) {
    u64 r;
    asm("mov.b64 %0, {%1, %2};" : "=l"(r) : "f"(lo), "f"(hi));
    return r;
}
__device__ __forceinline__ float hadd2(u64 v) {
    float lo, hi;
    asm("mov.b64 {%0, %1}, %2;" : "=f"(lo), "=f"(hi) : "l"(v));
    return lo + hi;
}

// ---------------------------------------------------------------------------
// Kernel 1: V = Wlin(2x64) @ Wt(64x3200), float4 loads for MLP.
// (Best measured prep shape; unchanged.)
// ---------------------------------------------------------------------------
__global__ void __launch_bounds__(128) prep_kernel(const float* __restrict__ Wt,
                                                   const float* __restrict__ bias,
                                                   const float* __restrict__ Wlin,
                                                   const float* __restrict__ blin) {
    __shared__ float4 r0[16][8];
    __shared__ float4 r1[16][8];
    const float4* Wt4 = reinterpret_cast<const float4*>(Wt);

    int og  = threadIdx.x >> 3;          // 0..15
    int j4l = threadIdx.x & 7;           // 0..7
    int j4g = blockIdx.x * 8 + j4l;      // 0..799

    float4 s0 = make_float4(0.f, 0.f, 0.f, 0.f);
    float4 s1 = make_float4(0.f, 0.f, 0.f, 0.f);
    #pragma unroll
    for (int oo = 0; oo < 4; oo++) {
        int o = og * 4 + oo;
        float4 wv = Wt4[o * CP4 + j4g];  // LDG.128, 4 independent per thread
        float w0 = __ldg(&Wlin[o]);
        float w1 = __ldg(&Wlin[O + o]);
        s0.x = fmaf(w0, wv.x, s0.x); s0.y = fmaf(w0, wv.y, s0.y);
        s0.z = fmaf(w0, wv.z, s0.z); s0.w = fmaf(w0, wv.w, s0.w);
        s1.x = fmaf(w1, wv.x, s1.x); s1.y = fmaf(w1, wv.y, s1.y);
        s1.z = fmaf(w1, wv.z, s1.z); s1.w = fmaf(w1, wv.w, s1.w);
    }
    r0[og][j4l] = s0;
    r1[og][j4l] = s1;
    __syncthreads();

    if (threadIdx.x < 8) {
        float4 t0 = make_float4(0.f, 0.f, 0.f, 0.f);
        float4 t1 = make_float4(0.f, 0.f, 0.f, 0.f);
        #pragma unroll
        for (int g = 0; g < 16; g++) {
            float4 a = r0[g][threadIdx.x];
            float4 b = r1[g][threadIdx.x];
            t0.x += a.x; t0.y += a.y; t0.z += a.z; t0.w += a.w;
            t1.x += b.x; t1.y += b.y; t1.z += b.z; t1.w += b.w;
        }
        int jb = (blockIdx.x * 8 + threadIdx.x) * 4;
        const float* e0 = reinterpret_cast<const float*>(&t0);
        const float* e1 = reinterpret_cast<const float*>(&t1);
        #pragma unroll
        for (int e = 0; e < 4; e++) {
            int j = jb + e;
            int c = j / P, p = j % P;
            g_V[p * C + c]       = e0[e];   // class 0 rows
            g_V[(P + p) * C + c] = e1[e];   // class 1 rows
        }
    }

    if (blockIdx.x == 0 && threadIdx.x < NC) {
        float s = blin[threadIdx.x];
        #pragma unroll
        for (int o = 0; o < O; o++) s += bias[o] * Wlin[threadIdx.x * O + o];
        g_const[threadIdx.x] = s;
    }
}

// ---------------------------------------------------------------------------
// Kernel 2: projection, weights from __constant__ (LDC port, LSU-free).
// 392 blocks x 128 threads, 1 px/thread, class per warp-pair. LSU now only
// carries 4 coalesced x-loads + 25 stores per thread; FMA pipe is the floor.
// ---------------------------------------------------------------------------
__global__ void __launch_bounds__(128, 4) proj_kernel(const float* __restrict__ x) {
    int tid  = threadIdx.x;
    int k    = tid >> 6;                  // class per warp-pair (warp-uniform)
    int lane = tid & 63;
    int pix  = blockIdx.x * 64 + lane;    // 392*64 = 25088, exact

    int n  = pix / HW;
    int hw = pix % HW;
    const float* xb = x + (size_t)n * C * HW + hw;
    int kbase = k * P * C4;

    u64 acc[P];
    #pragma unroll
    for (int p = 0; p < P; p++) acc[p] = 0ull;

    #pragma unroll 4
    for (int c4 = 0; c4 < C4; c4++) {
        float x0 = xb[(c4 * 4 + 0) * HW];
        float x1 = xb[(c4 * 4 + 1) * HW];
        float x2 = xb[(c4 * 4 + 2) * HW];
        float x3 = xb[(c4 * 4 + 3) * HW];
        u64 xp01 = pack2(x0, x1);
        u64 xp23 = pack2(x2, x3);
        #pragma unroll
        for (int p = 0; p < P; p++) {
            ulonglong2 wv = c_V[kbase + p * C4 + c4];   // LDC.128, uniform
            fma2(acc[p], wv.x, xp01);
            fma2(acc[p], wv.y, xp23);
        }
    }

    // Y[n][p][hw][k]
    float* yb = g_Y + ((size_t)n * P * HW + hw) * 2 + k;
    #pragma unroll
    for (int p = 0; p < P; p++)
        yb[(size_t)p * HW * 2] = hadd2(acc[p]);
}

// ---------------------------------------------------------------------------
// Kernel 3: 5x5 gather + drift/exp epilogue, thread = (pixel, class).
// ---------------------------------------------------------------------------
__global__ void __launch_bounds__(128) final_kernel(float* __restrict__ out) {
    int t   = blockIdx.x * 128 + threadIdx.x;   // 392*128 = 50176, exact
    int pix = t >> 1;
    int k   = t & 1;
    int n  = pix / HW;
    int hw = pix % HW;
    int h  = hw / W;
    int w  = hw % W;

    const float* yb = g_Y + ((size_t)n * P * HW) * 2 + k;
    float ck = g_const[k];

    float sum = 0.f, as = 0.f, ys = 0.f, xs = 0.f;

    #pragma unroll
    for (int i = 0; i < KS; i++) {
        int hh = h + i - 2;
        bool hin = (hh >= 0) && (hh < H);
        #pragma unroll
        for (int j = 0; j < KS; j++) {
            int ww = w + j - 2;
            bool in = hin && (ww >= 0) && (ww < W);
            int p = i * KS + j;
            float v = in ? yb[((size_t)p * HW + hh * W + ww) * 2] : 0.f;
            float m = v + ck;
            float a = fabsf(m);
            sum += m;
            as  += a;
            ys  = fmaf(a, (float)(i - 2), ys);
            xs  = fmaf(a, (float)(j - 2), xs);
        }
    }

    float yd = __fdividef(ys, as);
    float xd = __fdividef(xs, as);
    float d  = sqrtf(fmaf(xd, xd, yd * yd));
    out[pix * 2 + k] = sum * __expf(-0.5f * d);
}

// ---------------------------------------------------------------------------
extern "C" void kernel_launch(void* const* d_in, const int* in_sizes, int n_in,
                              void* d_out, int out_size) {
    const float* x    = (const float*)d_in[0];  // (8,128,56,56)
    const float* Wt   = (const float*)d_in[1];  // (64,128,5,5)
    const float* bias = (const float*)d_in[2];  // (64,)
    const float* Wlin = (const float*)d_in[3];  // (2,64)
    const float* blin = (const float*)d_in[4];  // (2,)
    float* out = (float*)d_out;                 // (8,56,56,2)

    prep_kernel<<<100, 128>>>(Wt, bias, Wlin, blin);

    // Stage folded weights into constant memory (D2D async: capturable, no alloc).
    void* vptr = nullptr;
    cudaGetSymbolAddress(&vptr, g_V);
    cudaMemcpyToSymbolAsync(c_V, vptr, sizeof(float) * P2 * C, 0,
                            cudaMemcpyDeviceToDevice, 0);

    proj_kernel<<<392, 128>>>(x);
    final_kernel<<<392, 128>>>(out);
}

// round 17
// speedup vs baseline: 10.2325x; 10.2325x over previous
#include <cuda_runtime.h>
#include <math.h>

#define NB   8
#define C    128
#define H    56
#define W    56
#define O    64
#define NC   2
#define KS   5
#define P    25
#define P2   50           // NC * P
#define HW   (H * W)      // 3136
#define PIX  (NB * HW)    // 25088
#define CP   (C * P)      // 3200
#define CP4  (CP / 4)     // 800 float4 per o-row
#define C4   (C / 4)      // 32
#define PAIRS (PIX / 2)   // 12544 pixel-pairs per class
#define PPBLK 85          // ceil(PAIRS / 148)

typedef unsigned long long u64;

// Scratch (allocation-free rule: __device__ globals)
__device__ __align__(16) float g_V[P2 * C];  // folded weights V[k*P+p][c]
__device__ float g_const[NC];                // per-class constant
__device__ float g_Y[NB * P * HW * 2];       // Y[n][p][hw][{class0,class1}]

__device__ __forceinline__ void fma2(u64& d, u64 a, u64 b) {
    asm("fma.rn.f32x2 %0, %1, %2, %0;" : "+l"(d) : "l"(a), "l"(b));
}
__device__ __forceinline__ u64 pack2(float lo, float hi) {
    u64 r;
    asm("mov.b64 %0, {%1, %2};" : "=l"(r) : "f"(lo), "f"(hi));
    return r;
}
__device__ __forceinline__ float hadd2(u64 v) {
    float lo, hi;
    asm("mov.b64 {%0, %1}, %2;" : "=f"(lo), "=f"(hi) : "l"(v));
    return lo + hi;
}

// ---------------------------------------------------------------------------
// Kernel 1: V = Wlin(2x64) @ Wt(64x3200), float4 loads for MLP.
// (Best measured prep shape; unchanged from R13.)
// ---------------------------------------------------------------------------
__global__ void __launch_bounds__(128) prep_kernel(const float* __restrict__ Wt,
                                                   const float* __restrict__ bias,
                                                   const float* __restrict__ Wlin,
                                                   const float* __restrict__ blin) {
    __shared__ float4 r0[16][8];
    __shared__ float4 r1[16][8];
    const float4* Wt4 = reinterpret_cast<const float4*>(Wt);

    int og  = threadIdx.x >> 3;          // 0..15
    int j4l = threadIdx.x & 7;           // 0..7
    int j4g = blockIdx.x * 8 + j4l;      // 0..799

    float4 s0 = make_float4(0.f, 0.f, 0.f, 0.f);
    float4 s1 = make_float4(0.f, 0.f, 0.f, 0.f);
    #pragma unroll
    for (int oo = 0; oo < 4; oo++) {
        int o = og * 4 + oo;
        float4 wv = Wt4[o * CP4 + j4g];  // LDG.128, 4 independent per thread
        float w0 = __ldg(&Wlin[o]);
        float w1 = __ldg(&Wlin[O + o]);
        s0.x = fmaf(w0, wv.x, s0.x); s0.y = fmaf(w0, wv.y, s0.y);
        s0.z = fmaf(w0, wv.z, s0.z); s0.w = fmaf(w0, wv.w, s0.w);
        s1.x = fmaf(w1, wv.x, s1.x); s1.y = fmaf(w1, wv.y, s1.y);
        s1.z = fmaf(w1, wv.z, s1.z); s1.w = fmaf(w1, wv.w, s1.w);
    }
    r0[og][j4l] = s0;
    r1[og][j4l] = s1;
    __syncthreads();

    if (threadIdx.x < 8) {
        float4 t0 = make_float4(0.f, 0.f, 0.f, 0.f);
        float4 t1 = make_float4(0.f, 0.f, 0.f, 0.f);
        #pragma unroll
        for (int g = 0; g < 16; g++) {
            float4 a = r0[g][threadIdx.x];
            float4 b = r1[g][threadIdx.x];
            t0.x += a.x; t0.y += a.y; t0.z += a.z; t0.w += a.w;
            t1.x += b.x; t1.y += b.y; t1.z += b.z; t1.w += b.w;
        }
        int jb = (blockIdx.x * 8 + threadIdx.x) * 4;
        const float* e0 = reinterpret_cast<const float*>(&t0);
        const float* e1 = reinterpret_cast<const float*>(&t1);
        #pragma unroll
        for (int e = 0; e < 4; e++) {
            int j = jb + e;
            int c = j / P, p = j % P;
            g_V[p * C + c]       = e0[e];   // class 0 rows
            g_V[(P + p) * C + c] = e1[e];   // class 1 rows
        }
    }

    if (blockIdx.x == 0 && threadIdx.x < NC) {
        float s = blin[threadIdx.x];
        #pragma unroll
        for (int o = 0; o < O; o++) s += bias[o] * Wlin[threadIdx.x * O + o];
        g_const[threadIdx.x] = s;
    }
}

// ---------------------------------------------------------------------------
// Kernel 2: projection. 148 blocks x 192 threads (3 warps per class-half;
// 85 pairs <= 96 slots, so no fully-idle warp). Perfectly balanced: 85
// adjacent-pixel pairs per block per class on every SM.
//  - class per 96-thread half -> weight LDG.128 warp-uniform, L1-resident
//  - adjacent pixels -> x fetched as LDG.64 (half the x-load instructions)
//  - each weight load feeds 4 FMA2 (2x amortization vs 1px/thread)
// ---------------------------------------------------------------------------
__global__ void __launch_bounds__(192) proj_kernel(const float* __restrict__ x) {
    int tid  = threadIdx.x;
    int k    = (tid >= 96) ? 1 : 0;       // class per block-half (warp-uniform)
    int slot = (k == 1) ? tid - 96 : tid; // 0..95
    int idx  = blockIdx.x * PPBLK + slot; // pixel-pair index
    if (slot >= PPBLK || idx >= PAIRS) return;

    int pix = idx * 2;                    // even -> pair stays inside one n
    int n   = pix / HW;
    int hw  = pix % HW;                   // even -> float2 loads 8B-aligned
    const float* xb = x + (size_t)n * C * HW + hw;

    const ulonglong2* __restrict__ Vk =
        reinterpret_cast<const ulonglong2*>(g_V) + (size_t)k * P * C4;

    u64 accA[P], accB[P];
    #pragma unroll
    for (int p = 0; p < P; p++) { accA[p] = 0ull; accB[p] = 0ull; }

    #pragma unroll 2
    for (int c4 = 0; c4 < C4; c4++) {
        float2 v0 = *reinterpret_cast<const float2*>(xb + (c4 * 4 + 0) * HW);
        float2 v1 = *reinterpret_cast<const float2*>(xb + (c4 * 4 + 1) * HW);
        float2 v2 = *reinterpret_cast<const float2*>(xb + (c4 * 4 + 2) * HW);
        float2 v3 = *reinterpret_cast<const float2*>(xb + (c4 * 4 + 3) * HW);
        u64 ap01 = pack2(v0.x, v1.x);     // pixel 0, channels (c0,c1)
        u64 ap23 = pack2(v2.x, v3.x);
        u64 bp01 = pack2(v0.y, v1.y);     // pixel 1
        u64 bp23 = pack2(v2.y, v3.y);
        #pragma unroll
        for (int p = 0; p < P; p++) {
            ulonglong2 wv = Vk[p * C4 + c4];   // uniform LDG.128, L1-hit
            fma2(accA[p], wv.x, ap01);
            fma2(accA[p], wv.y, ap23);
            fma2(accB[p], wv.x, bp01);
            fma2(accB[p], wv.y, bp23);
        }
    }

    // Y[n][p][hw][k]; pixel pair -> offsets hw*2+k and hw*2+2+k
    float* ya = g_Y + ((size_t)n * P * HW + hw) * 2 + k;
    #pragma unroll
    for (int p = 0; p < P; p++) {
        ya[(size_t)p * HW * 2]     = hadd2(accA[p]);
        ya[(size_t)p * HW * 2 + 2] = hadd2(accB[p]);
    }
}

// ---------------------------------------------------------------------------
// Kernel 3: 5x5 gather + drift/exp epilogue, thread = (pixel, class).
// (Unchanged from R13 best.)
// ---------------------------------------------------------------------------
__global__ void __launch_bounds__(128) final_kernel(float* __restrict__ out) {
    int t   = blockIdx.x * 128 + threadIdx.x;   // 392*128 = 50176, exact
    int pix = t >> 1;
    int k   = t & 1;
    int n  = pix / HW;
    int hw = pix % HW;
    int h  = hw / W;
    int w  = hw % W;

    const float* yb = g_Y + ((size_t)n * P * HW) * 2 + k;
    float ck = g_const[k];

    float sum = 0.f, as = 0.f, ys = 0.f, xs = 0.f;

    #pragma unroll
    for (int i = 0; i < KS; i++) {
        int hh = h + i - 2;
        bool hin = (hh >= 0) && (hh < H);
        #pragma unroll
        for (int j = 0; j < KS; j++) {
            int ww = w + j - 2;
            bool in = hin && (ww >= 0) && (ww < W);
            int p = i * KS + j;
            float v = in ? yb[((size_t)p * HW + hh * W + ww) * 2] : 0.f;
            float m = v + ck;
            float a = fabsf(m);
            sum += m;
            as  += a;
            ys  = fmaf(a, (float)(i - 2), ys);
            xs  = fmaf(a, (float)(j - 2), xs);
        }
    }

    float yd = __fdividef(ys, as);
    float xd = __fdividef(xs, as);
    float d  = sqrtf(fmaf(xd, xd, yd * yd));
    out[pix * 2 + k] = sum * __expf(-0.5f * d);
}

// ---------------------------------------------------------------------------
extern "C" void kernel_launch(void* const* d_in, const int* in_sizes, int n_in,
                              void* d_out, int out_size) {
    const float* x    = (const float*)d_in[0];  // (8,128,56,56)
    const float* Wt   = (const float*)d_in[1];  // (64,128,5,5)
    const float* bias = (const float*)d_in[2];  // (64,)
    const float* Wlin = (const float*)d_in[3];  // (2,64)
    const float* blin = (const float*)d_in[4];  // (2,)
    float* out = (float*)d_out;                 // (8,56,56,2)

    prep_kernel<<<100, 128>>>(Wt, bias, Wlin, blin);
    proj_kernel<<<148, 192>>>(x);               // balanced: 85 pairs/block
    final_kernel<<<392, 128>>>(out);
}